// round 4
// baseline (speedup 1.0000x reference)
#include <cuda_runtime.h>
#include <cuda_bf16.h>

#define CLASS_NUM 512
#define B_ROWS    1024
#define E_ROWS    50000
#define OUT_ELEMS (B_ROWS * E_ROWS)   // 51,200,000
#define N4        (OUT_ELEMS / 4)     // 12,800,000 float4 stores
#define E4        (E_ROWS / 4)        // 12,500 float4 per output row

// Scratch (no device allocation allowed): row partial sums.
__device__ float g_hr[B_ROWS];     // hr_part[b] + bias  (bias folded here)
__device__ float g_tail[E_ROWS];   // tail_part[e]

// ---------------------------------------------------------------------------
// Kernel 1: warp-per-row dot products.
// rows [0, B_ROWS)            -> g_hr[row]   = dot(hr[row],   W[0:512]) + b
// rows [B_ROWS, B_ROWS+E_ROWS)-> g_tail[r-B] = dot(tail[r-B], W[512:1024])
// Each row = 512 floats = 128 float4; 32 lanes x 4 float4 each.
// ---------------------------------------------------------------------------
__global__ void __launch_bounds__(256)
dot_kernel(const float* __restrict__ hr,
           const float* __restrict__ tail,
           const float* __restrict__ W,
           const float* __restrict__ bias)
{
    const int warp_id = (blockIdx.x * blockDim.x + threadIdx.x) >> 5;
    const int lane    = threadIdx.x & 31;
    const int total_rows = B_ROWS + E_ROWS;
    if (warp_id >= total_rows) return;

    const float* src;
    const float* w;
    if (warp_id < B_ROWS) {
        src = hr + (size_t)warp_id * CLASS_NUM;
        w   = W;                       // W1
    } else {
        src = tail + (size_t)(warp_id - B_ROWS) * CLASS_NUM;
        w   = W + CLASS_NUM;           // W2
    }

    const float4* s4 = reinterpret_cast<const float4*>(src);
    const float4* w4 = reinterpret_cast<const float4*>(w);

    float sum = 0.0f;
#pragma unroll
    for (int k = 0; k < 4; k++) {
        int j = lane + k * 32;         // 0..127
        float4 a = s4[j];
        float4 c = __ldg(&w4[j]);
        sum = fmaf(a.x, c.x, sum);
        sum = fmaf(a.y, c.y, sum);
        sum = fmaf(a.z, c.z, sum);
        sum = fmaf(a.w, c.w, sum);
    }
    // warp reduction
#pragma unroll
    for (int off = 16; off > 0; off >>= 1)
        sum += __shfl_xor_sync(0xFFFFFFFFu, sum, off);

    if (lane == 0) {
        if (warp_id < B_ROWS)
            g_hr[warp_id] = sum + __ldg(bias);
        else
            g_tail[warp_id - B_ROWS] = sum;
    }
}

// ---------------------------------------------------------------------------
// Kernel 2: broadcast outer sum, one float4 store per thread.
// out[b][e] = g_hr[b] + g_tail[e]   (bias already folded into g_hr)
// g_tail is 200 KB -> stays resident in L2 across all 1024 row passes.
// ---------------------------------------------------------------------------
__global__ void __launch_bounds__(256)
outer_kernel(float4* __restrict__ out)
{
    unsigned i = blockIdx.x * blockDim.x + threadIdx.x;
    if (i >= N4) return;
    unsigned b  = i / E4;          // constant divisor -> mul/shift in SASS
    unsigned e4 = i - b * E4;

    float h = g_hr[b];             // broadcast within warp -> 1 L1 line
    float4 t = *((const float4*)g_tail + e4);
    float4 r;
    r.x = h + t.x;
    r.y = h + t.y;
    r.z = h + t.z;
    r.w = h + t.w;
    out[i] = r;
}

// Zero any trailing elements beyond the scores matrix (reference returns
// (scores, 0); harness may append the scalar).
__global__ void zero_tail_kernel(float* __restrict__ out, int start, int total)
{
    int i = start + blockIdx.x * blockDim.x + threadIdx.x;
    if (i < total) out[i] = 0.0f;
}

extern "C" void kernel_launch(void* const* d_in, const int* in_sizes, int n_in,
                              void* d_out, int out_size)
{
    const float* hr   = (const float*)d_in[0];  // [1024, 512]
    const float* tail = (const float*)d_in[1];  // [50000, 512]
    const float* W    = (const float*)d_in[2];  // [1, 1024]
    const float* bias = (const float*)d_in[3];  // [1]
    float* out = (float*)d_out;

    // Kernel 1: (1024 + 50000) rows, 8 warps per 256-thread block.
    {
        int total_rows = B_ROWS + E_ROWS;
        int warps_per_block = 256 / 32;
        int blocks = (total_rows + warps_per_block - 1) / warps_per_block;
        dot_kernel<<<blocks, 256>>>(hr, tail, W, bias);
    }

    // Kernel 2: 12.8M float4 stores.
    {
        int blocks = (N4 + 255) / 256;
        outer_kernel<<<blocks, 256>>>((float4*)out);
    }

    // Zero any extra output elements (e.g. the appended scalar 0).
    if (out_size > OUT_ELEMS) {
        int extra = out_size - OUT_ELEMS;
        int blocks = (extra + 255) / 256;
        zero_tail_kernel<<<blocks, 256>>>(out, OUT_ELEMS, out_size);
    }
}

// round 6
// speedup vs baseline: 1.0638x; 1.0638x over previous
#include <cuda_runtime.h>
#include <cuda_bf16.h>

#define CLASS_NUM 512
#define B_ROWS    1024
#define E_ROWS    50000
#define OUT_ELEMS (B_ROWS * E_ROWS)   // 51,200,000
#define E4        (E_ROWS / 4)        // 12,500 float4 per output row

// Row-chunking for the outer kernel: each thread handles one e4 and a chunk
// of rows, so g_tail is read exactly once from L2 instead of 1024 times.
#define ROW_CHUNK 64
#define NUM_CHUNKS (B_ROWS / ROW_CHUNK)   // 16

// Scratch (no device allocation allowed): row partial sums.
__device__ float g_hr[B_ROWS];     // hr_part[b] + bias  (bias folded here)
__device__ float g_tail[E_ROWS];   // tail_part[e]

// ---------------------------------------------------------------------------
// Kernel 1: warp-per-row dot products.
// rows [0, B_ROWS)             -> g_hr[row]   = dot(hr[row],   W[0:512]) + b
// rows [B_ROWS, B_ROWS+E_ROWS) -> g_tail[r-B] = dot(tail[r-B], W[512:1024])
// Each row = 512 floats = 128 float4; 32 lanes x 4 float4 each.
// tail is streamed (never reused) -> __ldcs to avoid L2 pollution.
// ---------------------------------------------------------------------------
__global__ void __launch_bounds__(256)
dot_kernel(const float* __restrict__ hr,
           const float* __restrict__ tail,
           const float* __restrict__ W,
           const float* __restrict__ bias)
{
    const int warp_id = (blockIdx.x * blockDim.x + threadIdx.x) >> 5;
    const int lane    = threadIdx.x & 31;
    const int total_rows = B_ROWS + E_ROWS;
    if (warp_id >= total_rows) return;

    float sum = 0.0f;

    if (warp_id < B_ROWS) {
        const float4* s4 = reinterpret_cast<const float4*>(hr + (size_t)warp_id * CLASS_NUM);
        const float4* w4 = reinterpret_cast<const float4*>(W);
#pragma unroll
        for (int k = 0; k < 4; k++) {
            int j = lane + k * 32;
            float4 a = __ldg(&s4[j]);
            float4 c = __ldg(&w4[j]);
            sum = fmaf(a.x, c.x, sum);
            sum = fmaf(a.y, c.y, sum);
            sum = fmaf(a.z, c.z, sum);
            sum = fmaf(a.w, c.w, sum);
        }
    } else {
        const float4* s4 = reinterpret_cast<const float4*>(tail + (size_t)(warp_id - B_ROWS) * CLASS_NUM);
        const float4* w4 = reinterpret_cast<const float4*>(W + CLASS_NUM);
#pragma unroll
        for (int k = 0; k < 4; k++) {
            int j = lane + k * 32;
            float4 a = __ldcs(&s4[j]);   // streaming read, evict-first
            float4 c = __ldg(&w4[j]);
            sum = fmaf(a.x, c.x, sum);
            sum = fmaf(a.y, c.y, sum);
            sum = fmaf(a.z, c.z, sum);
            sum = fmaf(a.w, c.w, sum);
        }
    }

#pragma unroll
    for (int off = 16; off > 0; off >>= 1)
        sum += __shfl_xor_sync(0xFFFFFFFFu, sum, off);

    if (lane == 0) {
        if (warp_id < B_ROWS)
            g_hr[warp_id] = sum + __ldg(bias);
        else
            g_tail[warp_id - B_ROWS] = sum;
    }
}

// ---------------------------------------------------------------------------
// Kernel 2: broadcast outer sum, LOOP-INVERTED.
// Each thread owns one float4 of tail_part (read ONCE into a register),
// then streams out[b][e4] = g_hr[b] + t for a 64-row chunk of b.
// L2 read traffic: 205 MB -> ~0.2 MB. Output stored with __stcs (evict-first).
//
// grid: x covers e4 tiles (ceil(12500/256)=49), y covers row chunks (16).
// ---------------------------------------------------------------------------
__global__ void __launch_bounds__(256)
outer_kernel(float4* __restrict__ out)
{
    __shared__ float sh_hr[ROW_CHUNK];

    const int row0 = blockIdx.y * ROW_CHUNK;
    if (threadIdx.x < ROW_CHUNK)
        sh_hr[threadIdx.x] = g_hr[row0 + threadIdx.x];
    __syncthreads();

    const int e4 = blockIdx.x * blockDim.x + threadIdx.x;
    if (e4 >= E4) return;

    const float4 t = *((const float4*)g_tail + e4);

    float4* dst = out + (size_t)row0 * E4 + e4;
#pragma unroll 4
    for (int r = 0; r < ROW_CHUNK; r++) {
        const float h = sh_hr[r];
        float4 v;
        v.x = h + t.x;
        v.y = h + t.y;
        v.z = h + t.z;
        v.w = h + t.w;
        __stcs(dst, v);              // streaming store, evict-first
        dst += E4;
    }
}

// Zero any trailing elements beyond the scores matrix (reference returns
// (scores, 0); harness may append the scalar).
__global__ void zero_tail_kernel(float* __restrict__ out, int start, int total)
{
    int i = start + blockIdx.x * blockDim.x + threadIdx.x;
    if (i < total) out[i] = 0.0f;
}

extern "C" void kernel_launch(void* const* d_in, const int* in_sizes, int n_in,
                              void* d_out, int out_size)
{
    const float* hr   = (const float*)d_in[0];  // [1024, 512]
    const float* tail = (const float*)d_in[1];  // [50000, 512]
    const float* W    = (const float*)d_in[2];  // [1, 1024]
    const float* bias = (const float*)d_in[3];  // [1]
    float* out = (float*)d_out;

    // Kernel 1: (1024 + 50000) rows, 8 warps per 256-thread block.
    {
        int total_rows = B_ROWS + E_ROWS;
        int warps_per_block = 256 / 32;
        int blocks = (total_rows + warps_per_block - 1) / warps_per_block;
        dot_kernel<<<blocks, 256>>>(hr, tail, W, bias);
    }

    // Kernel 2: loop-inverted outer sum.
    {
        dim3 grid((E4 + 255) / 256, NUM_CHUNKS);
        outer_kernel<<<grid, 256>>>((float4*)out);
    }

    // Zero any extra output elements (e.g. the appended scalar 0).
    if (out_size > OUT_ELEMS) {
        int extra = out_size - OUT_ELEMS;
        int blocks = (extra + 255) / 256;
        zero_tail_kernel<<<blocks, 256>>>(out, OUT_ELEMS, out_size);
    }
}